// round 17
// baseline (speedup 1.0000x reference)
#include <cuda_runtime.h>

#define N_PTS   8192
#define C_DIM   64
#define C4      (C_DIM/4)
#define NQ      (3*N_PTS)                 // 24576 queries
#define VOFF    ((size_t)4*N_PTS*C_DIM)   // float offset of out_coords

#define G       64
#define NCELL   (G*G)                     // 4096 cells
#define HC      0.015625f                 // 1/64, exact in fp32

#define TPB     256
#define GRID    128                       // <=148 SMs -> co-resident always
#define QCT     192                       // queries per CTA (NQ/GRID)
#define NITEM   (N_PTS*C4 + N_PTS)        // 139264 copy items
#define CITM    (NITEM/GRID)              // 1088 copy items per CTA (exact)
#define FULL    0xffffffffu

typedef unsigned long long u64;
typedef unsigned int       u32;

// Row-major-cell CSR (rebuilt every launch; g_cnt re-zeroed in the tail so
// every launch/replay enters with a clean histogram).
__device__ int    g_cnt[NCELL];           // zero at entry (module init / tail)
__device__ int    g_start[NCELL + 1];
__device__ int    g_cur[NCELL];
__device__ float4 g_pts[N_PTS];           // (x, y, |c|^2, idx bits), CSR order

// Grid-barrier counters (self-resetting; replay-safe).
__device__ volatile int g_arr[3];
__device__ int          g_dep[3];

__device__ __forceinline__ int clamp_cell(float v) {
    int c = (int)floorf(v * 64.0f);
    return min(max(c, 0), G - 1);
}

// Grid barrier over GRID co-resident CTAs (arrive + spin + last-out reset).
__device__ __forceinline__ void gbar(int b) {
    __syncthreads();
    if (threadIdx.x == 0) {
        __threadfence();
        atomicAdd((int*)&g_arr[b], 1);
        while (g_arr[b] != GRID) __nanosleep(32);
        int p = atomicAdd(&g_dep[b], 1);
        if (p == GRID - 1) {
            g_dep[b] = 0;
            __threadfence();
            *(int*)&g_arr[b] = 0;
        }
    }
    __syncthreads();
}

// ---------------------------------------------------------------------------
// Single fused persistent kernel:
//   1. histogram (threads with gi < N_PTS)
//   2. gbar0; CTA0: prefix scan | CTAs 1..127: all output copies
//   3. gbar1; CSR scatter
//   4. gbar2; per-thread exact NN queries (192/CTA) + re-zero histogram
//   5. CTA-local winner gather (coalesced)
// ---------------------------------------------------------------------------
__global__ void __launch_bounds__(TPB)
fused(const float2* __restrict__ c2,
      const float*  __restrict__ spacing,
      const float*  __restrict__ shift,
      const float4* __restrict__ val4,
      float*        __restrict__ out)
{
    __shared__ int widx[QCT];
    const int t  = threadIdx.x;
    const int b  = blockIdx.x;
    const int gi = b * TPB + t;             // 0..32767

    float s0  = __ldg(&spacing[0]), s1  = __ldg(&spacing[1]);
    float sh0 = __ldg(&shift[0]),   sh1 = __ldg(&shift[1]);

    // ---- phase 1: histogram (g_cnt zero at entry by invariant) ----
    float2 cpt;  int cell = 0;
    const bool own_pt = (gi < N_PTS);
    if (own_pt) {
        cpt  = __ldg(&c2[gi]);
        cell = clamp_cell(cpt.y) * G + clamp_cell(cpt.x);
        atomicAdd(&g_cnt[cell], 1);
    }
    gbar(0);

    // ---- phase 2: CTA0 scans; everyone else copies ----
    if (b == 0) {
        __shared__ int wsum[8];
        const int lane = t & 31, w = t >> 5;
        int v[16], s = 0;
        #pragma unroll
        for (int k = 0; k < 16; k++) {
            v[k] = __ldcg(&g_cnt[t * 16 + k]);
            s += v[k];
        }
        int inc = s;
        #pragma unroll
        for (int o = 1; o < 32; o <<= 1) {
            int n = __shfl_up_sync(FULL, inc, o);
            if (lane >= o) inc += n;
        }
        if (lane == 31) wsum[w] = inc;
        __syncthreads();
        if (t < 8) {
            int x = wsum[t];
            #pragma unroll
            for (int o = 1; o < 8; o <<= 1) {
                int n = __shfl_up_sync(0xffu, x, o);
                if (t >= o) x += n;
            }
            wsum[t] = x;
        }
        __syncthreads();
        int run = (inc - s) + (w ? wsum[w - 1] : 0);
        #pragma unroll
        for (int k = 0; k < 16; k++) {
            g_start[t * 16 + k] = run;
            g_cur[t * 16 + k]   = run;
            run += v[k];
        }
        if (t == 255) g_start[NCELL] = run;   // = N_PTS
    }

    // output copies (independent of binning): CTAs 1..127 cover everything;
    // CTA0's share is folded into CTA1..127 via CITM*GRID == NITEM exactly,
    // so CTA0 also takes its slice AFTER its scan (cheap).
    {
        const int base = b * CITM;
        #pragma unroll
        for (int k = 0; k < 5; k++) {
            int off = k * TPB + t;
            if (off < CITM) {
                int item = base + off;
                if (item < N_PTS * C4) {
                    reinterpret_cast<float4*>(out)[item] = __ldg(&val4[item]);
                } else {
                    int i = item - N_PTS * C4;
                    float2 cc = __ldg(&c2[i]);
                    float xs = __fadd_rn(cc.x, s0);
                    float ys = __fadd_rn(cc.y, s1);
                    float2* outc = reinterpret_cast<float2*>(out + VOFF);
                    outc[i]             = cc;
                    outc[N_PTS   + i]   = make_float2(xs,   ys);
                    outc[2*N_PTS + i]   = make_float2(cc.x, ys);
                    outc[3*N_PTS + i]   = make_float2(xs,   cc.y);
                }
            }
        }
    }
    gbar(1);

    // ---- phase 3: CSR scatter ----
    if (own_pt) {
        float sc = __fadd_rn(__fmul_rn(cpt.x, cpt.x), __fmul_rn(cpt.y, cpt.y));
        int pos = atomicAdd(&g_cur[cell], 1);
        g_pts[pos] = make_float4(cpt.x, cpt.y, sc, __int_as_float(gi));
    }
    gbar(2);

    // restore zero-histogram invariant for the next launch/replay
    if (gi < NCELL) g_cnt[gi] = 0;

    // ---- phase 4: per-thread exact NN (threads 0..QCT-1) ----
    if (t < QCT) {
        const int q = b * QCT + t;          // 0..24575
        const int g = q >> 13;
        const int i = q & (N_PTS - 1);

        float2 c = __ldg(&c2[i]);
        float nc0, nc1;
        if (g == 0)      { nc0 = __fadd_rn(c.x, s0); nc1 = __fadd_rn(c.y, s1); }
        else if (g == 1) { nc0 = c.x;                nc1 = __fadd_rn(c.y, s1); }
        else             { nc0 = __fadd_rn(c.x, s0); nc1 = c.y;                }

        const float a0 = __fsub_rn(nc0, sh0);
        const float a1 = __fsub_rn(nc1, sh1);
        const float sa = __fadd_rn(__fmul_rn(a0, a0), __fmul_rn(a1, a1));

        const int cx = clamp_cell(a0);
        const int cy = clamp_cell(a1);

        const float dxo = fmaxf(fmaxf(a0 - 1.0f, -a0), 0.0f);
        const float dyo = fmaxf(fmaxf(a1 - 1.0f, -a1), 0.0f);
        const float dxo2 = dxo * dxo;
        const float dyo2 = dyo * dyo;

        u64 bestk = ~0ull;

        // exact per-pair semantics (verified bit-identical to reference):
        //   m = fma(a1, py, RN(a0*px));  d = fma(m, -2, RN(sa+sc))
        #define EVAL_PT(P) do {                                              \
            float m_ = __fmaf_rn(a1, (P).y, __fmul_rn(a0, (P).x));           \
            float d_ = __fmaf_rn(m_, -2.0f, __fadd_rn(sa, (P).z));           \
            u32 ub_ = __float_as_uint(d_);                                   \
            ub_ = (ub_ & 0x80000000u) ? ~ub_ : (ub_ | 0x80000000u);          \
            u64 key_ = ((u64)ub_ << 32) | (u32)__float_as_uint((P).w);       \
            bestk = (key_ < bestk) ? key_ : bestk;                           \
        } while (0)

        #define LB2(x0_, x1_, y0_, y1_, out_) do {                           \
            float l_ = __int_as_float(0x7f800000);                           \
            if ((x0_) > 0) {                                                 \
                float dx = fmaxf(__fsub_rn(a0, (float)(x0_) * HC), 0.0f);    \
                l_ = fminf(l_, __fmaf_rn(dx, dx, dyo2));                     \
            }                                                                \
            if ((x1_) < G - 1) {                                             \
                float dx = fmaxf(__fsub_rn((float)((x1_)+1) * HC, a0), 0.0f);\
                l_ = fminf(l_, __fmaf_rn(dx, dx, dyo2));                     \
            }                                                                \
            if ((y0_) > 0) {                                                 \
                float dy = fmaxf(__fsub_rn(a1, (float)(y0_) * HC), 0.0f);    \
                l_ = fminf(l_, __fmaf_rn(dy, dy, dxo2));                     \
            }                                                                \
            if ((y1_) < G - 1) {                                             \
                float dy = fmaxf(__fsub_rn((float)((y1_)+1) * HC, a1), 0.0f);\
                l_ = fminf(l_, __fmaf_rn(dy, dy, dxo2));                     \
            }                                                                \
            (out_) = l_;                                                     \
        } while (0)

        // fast path: 3x3 clipped square = 3 contiguous CSR row intervals,
        // scanned as ONE flat predicated loop (divergence = max tot in warp)
        {
            const int x0 = max(cx - 1, 0), x1 = min(cx + 1, G - 1);
            const int y0 = max(cy - 1, 0), y1 = min(cy + 1, G - 1);

            int s0r, e0r, s1r, e1r, s2r, e2r;
            {
                int ya = cy - 1, yc = cy + 1, b1 = cy * G;
                bool va = (ya >= 0), vc = (yc <= G - 1);
                s0r = va ? __ldg(&g_start[ya * G + x0])     : 0;
                e0r = va ? __ldg(&g_start[ya * G + x1 + 1]) : 0;
                s1r = __ldg(&g_start[b1 + x0]);
                e1r = __ldg(&g_start[b1 + x1 + 1]);
                s2r = vc ? __ldg(&g_start[yc * G + x0])     : 0;
                e2r = vc ? __ldg(&g_start[yc * G + x1 + 1]) : 0;
            }
            const int l0 = e0r - s0r, l1 = e1r - s1r;
            const int o1 = l0, o2 = l0 + l1;
            const int tot = o2 + (e2r - s2r);

            #pragma unroll 4
            for (int k = 0; k < tot; k++) {
                int idx = (k < o1) ? (s0r + k)
                        : (k < o2) ? (s1r + (k - o1))
                                   : (s2r + (k - o2));
                float4 p = __ldg(&g_pts[idx]);
                EVAL_PT(p);
            }

            float lb2; LB2(x0, x1, y0, y1, lb2);
            bool done_all = (lb2 > 1e18f);
            u32 mu = (u32)(bestk >> 32);
            float bd;
            if (mu == 0xffffffffu)      bd = __int_as_float(0x7f800000);
            else if (mu & 0x80000000u)  bd = __uint_as_float(mu & 0x7fffffffu);
            else                        bd = __uint_as_float(~mu);

            if (!done_all && !(lb2 > bd + 1e-4f)) {
                // slow path (~2-3% of queries): expanding squares, rescans
                // are min-safe; same termination bound each round.
                int r = 3;
                while (true) {
                    const int xx0 = max(cx - r, 0), xx1 = min(cx + r, G - 1);
                    const int yy0 = max(cy - r, 0), yy1 = min(cy + r, G - 1);
                    for (int y = yy0; y <= yy1; y++) {
                        int s = __ldg(&g_start[y * G + xx0]);
                        int e = __ldg(&g_start[y * G + xx1 + 1]);
                        #pragma unroll 4
                        for (int k = s; k < e; k++) {
                            float4 p = __ldg(&g_pts[k]);
                            EVAL_PT(p);
                        }
                    }
                    float l2; LB2(xx0, xx1, yy0, yy1, l2);
                    if (l2 > 1e18f) break;
                    u32 mu2 = (u32)(bestk >> 32);
                    float bd2;
                    if (mu2 == 0xffffffffu)     bd2 = __int_as_float(0x7f800000);
                    else if (mu2 & 0x80000000u) bd2 = __uint_as_float(mu2 & 0x7fffffffu);
                    else                        bd2 = __uint_as_float(~mu2);
                    if (l2 > bd2 + 1e-4f) break;
                    r = 2 * r + 1;
                }
            }
        }
        #undef EVAL_PT
        #undef LB2

        widx[t] = (int)(u32)(bestk & 0xFFFFFFFFull);
    }
    __syncthreads();

    // ---- phase 5: coalesced gather, 192 rows x 16 float4 per CTA ----
    {
        float4* outv4 = reinterpret_cast<float4*>(out);
        #pragma unroll
        for (int k = 0; k < QCT * C4 / TPB; k++) {      // 12 iterations
            int idx = k * TPB + t;
            int rr  = idx >> 4;
            int ccx = idx & (C4 - 1);
            int row = b * QCT + rr;
            outv4[(size_t)(N_PTS + row) * C4 + ccx] =
                __ldg(&val4[(size_t)widx[rr] * C4 + ccx]);
        }
    }
}

// ---------------------------------------------------------------------------
extern "C" void kernel_launch(void* const* d_in, const int* in_sizes, int n_in,
                              void* d_out, int out_size)
{
    const float4* val4    = (const float4*)d_in[0];
    const float2* c2      = (const float2*)d_in[1];
    const float*  spacing = (const float*) d_in[2];
    const float*  shift   = (const float*) d_in[3];
    float* out = (float*)d_out;

    fused<<<GRID, TPB>>>(c2, spacing, shift, val4, out);
}